// round 8
// baseline (speedup 1.0000x reference)
#include <cuda_runtime.h>
#include <cuda_fp16.h>
#include <cstdint>

#define NN 1024
#define DD 32
#define HH 64
#define LN_EPS 1e-5f
#define PADH 68   // smem row stride (floats): max 2-way conflicts

typedef unsigned long long ull;

// ---------------- device globals ----------------
__device__ float g_hs[NN * HH];        // X @ W1[:32]
__device__ float g_hd[NN * HH];        // X @ W1[32:] + b1
__device__ float g_hsum[NN];           // row sums of g_hs
__device__ float g_dsum[NN];           // row sums of g_hd
__device__ uint4 g_w2f[8 * 2 * 32];    // fp16 W2 B-frags: [nt][kkpair][lane] = {b0,b1 (kk even), b0,b1 (kk odd)}

// ---------------- packed f32x2 helpers ----------------
__device__ __forceinline__ ull p2_add(ull a, ull b) {
    ull r; asm("add.rn.f32x2 %0, %1, %2;" : "=l"(r) : "l"(a), "l"(b)); return r;
}
__device__ __forceinline__ ull p2_fma(ull a, ull b, ull c) {
    ull r; asm("fma.rn.f32x2 %0, %1, %2, %3;" : "=l"(r) : "l"(a), "l"(b), "l"(c)); return r;
}
__device__ __forceinline__ ull p2_pack(float lo, float hi) {
    ull r; asm("mov.b64 %0, {%1, %2};" : "=l"(r) : "f"(lo), "f"(hi)); return r;
}
__device__ __forceinline__ void p2_unpack(ull v, float& lo, float& hi) {
    asm("mov.b64 {%0, %1}, %2;" : "=f"(lo), "=f"(hi) : "l"(v));
}
__device__ __forceinline__ uint32_t pack_h2(float a, float b) {
    __half2 t = __floats2half2_rn(a, b);
    return *reinterpret_cast<uint32_t*>(&t);
}
__device__ __forceinline__ uint32_t relu_h2(ull v) {
    float a, b;
    p2_unpack(v, a, b);
    __half2 h = __floats2half2_rn(a, b);
    h = __hmax2(h, __half2half2(__ushort_as_half(0)));
    return *reinterpret_cast<uint32_t*>(&h);
}
__device__ __forceinline__ void mma_f16(float* c, uint32_t a0, uint32_t a1,
                                        uint32_t a2, uint32_t a3,
                                        uint32_t b0, uint32_t b1) {
    asm volatile(
        "mma.sync.aligned.m16n8k16.row.col.f32.f16.f16.f32 "
        "{%0,%1,%2,%3}, {%4,%5,%6,%7}, {%8,%9}, {%0,%1,%2,%3};"
        : "+f"(c[0]), "+f"(c[1]), "+f"(c[2]), "+f"(c[3])
        : "r"(a0), "r"(a1), "r"(a2), "r"(a3), "r"(b0), "r"(b1));
}
__device__ __forceinline__ float qred(float v) {
    v += __shfl_xor_sync(0xffffffffu, v, 1);
    v += __shfl_xor_sync(0xffffffffu, v, 2);
    return v;
}
__device__ __forceinline__ float wred32(float v) {
    #pragma unroll
    for (int s = 16; s > 0; s >>= 1) v += __shfl_xor_sync(0xffffffffu, v, s);
    return v;
}

// ---------------- merged prep ----------------
__global__ void prep_all(const float* __restrict__ X,
                         const float* __restrict__ W1,
                         const float* __restrict__ b1,
                         const float* __restrict__ W2) {
    if (blockIdx.x < 256) {
        __shared__ float xs[4][DD];
        __shared__ float red[4][HH];
        int sub = threadIdx.x >> 6;
        int n = threadIdx.x & 63;
        int i = blockIdx.x * 4 + sub;
        if (n < DD) xs[sub][n] = X[i * DD + n];
        __syncthreads();
        float hs = 0.f, hd = b1[n];
        #pragma unroll
        for (int d = 0; d < DD; d++) {
            float xv = xs[sub][d];
            hs = fmaf(xv, W1[d * HH + n], hs);
            hd = fmaf(xv, W1[(DD + d) * HH + n], hd);
        }
        g_hs[i * HH + n] = hs;
        g_hd[i * HH + n] = hd;
        red[sub][n] = hs;
        __syncthreads();
        if (n < 32) {
            float v = red[sub][n] + red[sub][n + 32];
            v = wred32(v);
            if (n == 0) g_hsum[i] = v;
        }
        __syncthreads();
        red[sub][n] = hd;
        __syncthreads();
        if (n < 32) {
            float v = red[sub][n] + red[sub][n + 32];
            v = wred32(v);
            if (n == 0) g_dsum[i] = v;
        }
    } else {
        // B-frags as uint4 per (nt, kkpair, lane): covers kk=2kp and kk=2kp+1
        int t = (blockIdx.x - 256) * 256 + threadIdx.x;   // 512 entries
        if (t >= 512) return;
        int lane = t & 31;
        int kp = (t >> 5) & 1;
        int nt = t >> 6;
        int n  = nt * 8 + (lane >> 2);
        int kq = kp * 32 + (lane & 3) * 2;
        uint4 r;
        r.x = pack_h2(W2[kq * HH + n],        W2[(kq + 1) * HH + n]);
        r.y = pack_h2(W2[(kq + 8) * HH + n],  W2[(kq + 9) * HH + n]);
        r.z = pack_h2(W2[(kq + 16) * HH + n], W2[(kq + 17) * HH + n]);
        r.w = pack_h2(W2[(kq + 24) * HH + n], W2[(kq + 25) * HH + n]);
        g_w2f[t] = r;
    }
}

// ---------------- main pair kernel ----------------
__global__ __launch_bounds__(128, 4) void pair_kernel(
    const float* __restrict__ g1, const float* __restrict__ be1,
    const float* __restrict__ b2, const float* __restrict__ g2,
    const float* __restrict__ be2, const float* __restrict__ W3,
    const float* __restrict__ b3, float* __restrict__ out) {
    __shared__ uint4 s_bf[8 * 2 * 32];                 // 8 KB
    __shared__ __align__(16) float s_hd[16 * PADH];
    __shared__ __align__(16) float s_hs[8 * PADH];
    __shared__ ulonglong2 s_p1[32];                    // {g1 pair, be1 pair}
    __shared__ ulonglong2 s_p2[32];                    // {g2 pair, be2 pair}
    __shared__ ull s_w3h[32];                          // 0.5*W3 pairs
    __shared__ __align__(8) float s_b2[HH];
    __shared__ float s_S[8], s_T[16], s_b3;

    int tid = threadIdx.x;
    int w = tid >> 5, lane = tid & 31;
    int qr = lane >> 2, qc = lane & 3;
    int bx = blockIdx.x, by = blockIdx.y;

    #pragma unroll
    for (int idx = tid; idx < 512; idx += 128) s_bf[idx] = g_w2f[idx];
    #pragma unroll
    for (int idx = tid; idx < 16 * 64; idx += 128) {
        int r = idx >> 6, c = idx & 63;
        s_hd[r * PADH + c] = g_hd[(bx * 16 + r) * HH + c];
    }
    #pragma unroll
    for (int idx = tid; idx < 8 * 64; idx += 128) {
        int r = idx >> 6, c = idx & 63;
        s_hs[r * PADH + c] = g_hs[(by * 8 + r) * HH + c];
    }
    if (tid < 32) {
        ulonglong2 p;
        p.x = p2_pack(g1[2 * tid],  g1[2 * tid + 1]);
        p.y = p2_pack(be1[2 * tid], be1[2 * tid + 1]);
        s_p1[tid] = p;
        p.x = p2_pack(g2[2 * tid],  g2[2 * tid + 1]);
        p.y = p2_pack(be2[2 * tid], be2[2 * tid + 1]);
        s_p2[tid] = p;
        s_w3h[tid] = p2_pack(0.5f * W3[2 * tid], 0.5f * W3[2 * tid + 1]);
    }
    if (tid < HH) s_b2[tid] = b2[tid];
    if (tid < 8)  s_S[tid] = g_hsum[by * 8 + tid];
    if (tid < 16) s_T[tid] = g_dsum[bx * 16 + tid];
    if (tid == 0) s_b3 = b3[0];
    __syncthreads();

    // ---- hd rows in registers (reused by both mtiles) ----
    const float* hdr1 = s_hd + qr * PADH;
    const float* hdr2 = s_hd + (qr + 8) * PADH;
    ull dA[8], dB[8];
    #pragma unroll
    for (int ci = 0; ci < 8; ci++) {
        int c = (ci >> 1) * 16 + (ci & 1) * 8 + qc * 2;
        dA[ci] = *reinterpret_cast<const ull*>(hdr1 + c);
        dB[ci] = *reinterpret_cast<const ull*>(hdr2 + c);
    }
    float Tv1 = s_T[qr], Tv2 = s_T[qr + 8];

    // ---- prologue: packed LN1 -> fp16 A frags ----
    uint32_t af[2][4][4];
    #pragma unroll
    for (int mt = 0; mt < 2; mt++) {
        const float* hsr = s_hs + (w * 2 + mt) * PADH;
        ull a[8];
        #pragma unroll
        for (int ci = 0; ci < 8; ci++) {
            int c = (ci >> 1) * 16 + (ci & 1) * 8 + qc * 2;
            a[ci] = *reinterpret_cast<const ull*>(hsr + c);
        }
        float Sv = s_S[w * 2 + mt];
        #pragma unroll
        for (int rr = 0; rr < 2; rr++) {
            const ull* D = rr ? dB : dA;
            float Tv = rr ? Tv2 : Tv1;
            ull x[8];
            ull s2p = 0ull;
            #pragma unroll
            for (int ci = 0; ci < 8; ci++) {
                x[ci] = p2_add(a[ci], D[ci]);
                s2p = p2_fma(x[ci], x[ci], s2p);
            }
            float lo, hi;
            p2_unpack(s2p, lo, hi);
            float s2 = qred(lo + hi);
            float mu = (Sv + Tv) * (1.f / HH);
            float rs = rsqrtf(s2 * (1.f / HH) - mu * mu + LN_EPS);
            ull rsp = p2_pack(rs, rs);
            ull nmp = p2_pack(-mu * rs, -mu * rs);
            #pragma unroll
            for (int ci = 0; ci < 8; ci++) {
                int kk = ci >> 1, h = ci & 1;
                int cp = (kk * 16 + h * 8 + qc * 2) >> 1;
                ulonglong2 P = s_p1[cp];
                ull v = p2_fma(p2_fma(x[ci], rsp, nmp), P.x, P.y);
                af[mt][kk][h * 2 + rr] = relu_h2(v);
            }
        }
    }

    // ---- fused MMA, acc initialized with b2 ----
    float acc[2][8][4];
    #pragma unroll
    for (int nt = 0; nt < 8; nt++) {
        int c = nt * 8 + qc * 2;
        ull b2p = *reinterpret_cast<const ull*>(s_b2 + c);
        float bxv, byv;
        p2_unpack(b2p, bxv, byv);
        #pragma unroll
        for (int mt = 0; mt < 2; mt++) {
            acc[mt][nt][0] = bxv; acc[mt][nt][1] = byv;
            acc[mt][nt][2] = bxv; acc[mt][nt][3] = byv;
        }
    }
    #pragma unroll
    for (int nt = 0; nt < 8; nt++) {
        #pragma unroll
        for (int kp = 0; kp < 2; kp++) {
            uint4 B = s_bf[(nt * 2 + kp) * 32 + lane];
            int k0 = 2 * kp, k1 = 2 * kp + 1;
            mma_f16(acc[0][nt], af[0][k0][0], af[0][k0][1], af[0][k0][2], af[0][k0][3], B.x, B.y);
            mma_f16(acc[1][nt], af[1][k0][0], af[1][k0][1], af[1][k0][2], af[1][k0][3], B.x, B.y);
            mma_f16(acc[0][nt], af[0][k1][0], af[0][k1][1], af[0][k1][2], af[0][k1][3], B.z, B.w);
            mma_f16(acc[1][nt], af[1][k1][0], af[1][k1][1], af[1][k1][2], af[1][k1][3], B.z, B.w);
        }
    }

    // ---- epilogue per mtile ----
    const ull ABSM = 0x7FFFFFFF7FFFFFFFull;
    #pragma unroll
    for (int mt = 0; mt < 2; mt++) {
        int i  = by * 8 + w * 2 + mt;
        int j1 = bx * 16 + qr;

        ull u1p[8], u2p[8];
        ull t11p = 0ull, t12p = 0ull, t21p = 0ull, t22p = 0ull;
        #pragma unroll
        for (int nt = 0; nt < 8; nt++) {
            ull ua = p2_pack(acc[mt][nt][0], acc[mt][nt][1]);
            ull ub = p2_pack(acc[mt][nt][2], acc[mt][nt][3]);
            u1p[nt] = ua; u2p[nt] = ub;
            t11p = p2_add(t11p, ua); t12p = p2_fma(ua, ua, t12p);
            t21p = p2_add(t21p, ub); t22p = p2_fma(ub, ub, t22p);
        }
        float lo, hi;
        p2_unpack(t11p, lo, hi); float t11 = qred(lo + hi);
        p2_unpack(t12p, lo, hi); float t12 = qred(lo + hi);
        p2_unpack(t21p, lo, hi); float t21 = qred(lo + hi);
        p2_unpack(t22p, lo, hi); float t22 = qred(lo + hi);
        float m1 = t11 * (1.f / HH);
        float r1 = rsqrtf(t12 * (1.f / HH) - m1 * m1 + LN_EPS);
        float m2 = t21 * (1.f / HH);
        float r2 = rsqrtf(t22 * (1.f / HH) - m2 * m2 + LN_EPS);
        ull r1p = p2_pack(r1, r1), nm1p = p2_pack(-m1 * r1, -m1 * r1);
        ull r2p = p2_pack(r2, r2), nm2p = p2_pack(-m2 * r2, -m2 * r2);

        ull d1p = 0ull, d2p = 0ull;
        #pragma unroll
        for (int nt = 0; nt < 8; nt++) {
            int cp = nt * 4 + qc;
            ulonglong2 P = s_p2[cp];
            ull w3p = s_w3h[cp];
            // relu(z)*w3 == (z + |z|) * (w3/2)  (exact)
            ull z1 = p2_fma(p2_fma(u1p[nt], r1p, nm1p), P.x, P.y);
            d1p = p2_fma(p2_add(z1, z1 & ABSM), w3p, d1p);
            ull z2 = p2_fma(p2_fma(u2p[nt], r2p, nm2p), P.x, P.y);
            d2p = p2_fma(p2_add(z2, z2 & ABSM), w3p, d2p);
        }
        p2_unpack(d1p, lo, hi); float d1 = qred(lo + hi);
        p2_unpack(d2p, lo, hi); float d2 = qred(lo + hi);
        if (qc == 0) {
            out[i * NN + j1]     = 1.f / (1.f + __expf(-(d1 + s_b3)));
            out[i * NN + j1 + 8] = 1.f / (1.f + __expf(-(d2 + s_b3)));
        }
    }
}

// ---------------- launch ----------------
extern "C" void kernel_launch(void* const* d_in, const int* in_sizes, int n_in,
                              void* d_out, int out_size) {
    const float* X   = (const float*)d_in[0];
    const float* W1  = (const float*)d_in[1];
    const float* b1  = (const float*)d_in[2];
    const float* g1  = (const float*)d_in[3];
    const float* be1 = (const float*)d_in[4];
    const float* W2  = (const float*)d_in[5];
    const float* b2  = (const float*)d_in[6];
    const float* g2  = (const float*)d_in[7];
    const float* be2 = (const float*)d_in[8];
    const float* W3  = (const float*)d_in[9];
    const float* b3  = (const float*)d_in[10];
    float* out = (float*)d_out;

    prep_all<<<258, 256>>>(X, W1, b1, W2);
    dim3 grid(NN / 16, NN / 8);
    pair_kernel<<<grid, 128>>>(g1, be1, b2, g2, be2, W3, b3, out);
}

// round 9
// speedup vs baseline: 1.0418x; 1.0418x over previous
#include <cuda_runtime.h>
#include <cuda_fp16.h>
#include <cstdint>

#define NN 1024
#define DD 32
#define HH 64
#define LN_EPS 1e-5f
#define PADH 68   // smem row stride (floats): max 2-way conflicts

typedef unsigned long long ull;

// ---------------- device globals ----------------
__device__ float g_hs[NN * HH];       // X @ W1[:32]
__device__ float g_hd[NN * HH];       // X @ W1[32:] + b1
__device__ float g_hsum[NN];          // row sums of g_hs
__device__ float g_dsum[NN];          // row sums of g_hd
__device__ uint2 g_w2f[8 * 4 * 32];   // fp16 W2 B-frags: [nt][kk][lane] = {b0,b1}

// ---------------- packed f32x2 helpers ----------------
__device__ __forceinline__ ull p2_add(ull a, ull b) {
    ull r; asm("add.rn.f32x2 %0, %1, %2;" : "=l"(r) : "l"(a), "l"(b)); return r;
}
__device__ __forceinline__ ull p2_fma(ull a, ull b, ull c) {
    ull r; asm("fma.rn.f32x2 %0, %1, %2, %3;" : "=l"(r) : "l"(a), "l"(b), "l"(c)); return r;
}
__device__ __forceinline__ ull p2_pack(float lo, float hi) {
    ull r; asm("mov.b64 %0, {%1, %2};" : "=l"(r) : "f"(lo), "f"(hi)); return r;
}
__device__ __forceinline__ void p2_unpack(ull v, float& lo, float& hi) {
    asm("mov.b64 {%0, %1}, %2;" : "=f"(lo), "=f"(hi) : "l"(v));
}
__device__ __forceinline__ uint32_t pack_h2(float a, float b) {
    __half2 t = __floats2half2_rn(a, b);
    return *reinterpret_cast<uint32_t*>(&t);
}
__device__ __forceinline__ void mma_f16(float* c, uint32_t a0, uint32_t a1,
                                        uint32_t a2, uint32_t a3,
                                        uint32_t b0, uint32_t b1) {
    asm volatile(
        "mma.sync.aligned.m16n8k16.row.col.f32.f16.f16.f32 "
        "{%0,%1,%2,%3}, {%4,%5,%6,%7}, {%8,%9}, {%0,%1,%2,%3};"
        : "+f"(c[0]), "+f"(c[1]), "+f"(c[2]), "+f"(c[3])
        : "r"(a0), "r"(a1), "r"(a2), "r"(a3), "r"(b0), "r"(b1));
}
__device__ __forceinline__ float qred(float v) {
    v += __shfl_xor_sync(0xffffffffu, v, 1);
    v += __shfl_xor_sync(0xffffffffu, v, 2);
    return v;
}
__device__ __forceinline__ float wred32(float v) {
    #pragma unroll
    for (int s = 16; s > 0; s >>= 1) v += __shfl_xor_sync(0xffffffffu, v, s);
    return v;
}

// ---------------- merged prep ----------------
__global__ void prep_all(const float* __restrict__ X,
                         const float* __restrict__ W1,
                         const float* __restrict__ b1,
                         const float* __restrict__ W2) {
    if (blockIdx.x < 256) {
        __shared__ float xs[4][DD];
        __shared__ float red[4][HH];
        int sub = threadIdx.x >> 6;
        int n = threadIdx.x & 63;
        int i = blockIdx.x * 4 + sub;
        if (n < DD) xs[sub][n] = X[i * DD + n];
        __syncthreads();
        float hs = 0.f, hd = b1[n];
        #pragma unroll
        for (int d = 0; d < DD; d++) {
            float xv = xs[sub][d];
            hs = fmaf(xv, W1[d * HH + n], hs);
            hd = fmaf(xv, W1[(DD + d) * HH + n], hd);
        }
        g_hs[i * HH + n] = hs;
        g_hd[i * HH + n] = hd;
        red[sub][n] = hs;
        __syncthreads();
        if (n < 32) {
            float v = red[sub][n] + red[sub][n + 32];
            v = wred32(v);
            if (n == 0) g_hsum[i] = v;
        }
        __syncthreads();
        red[sub][n] = hd;
        __syncthreads();
        if (n < 32) {
            float v = red[sub][n] + red[sub][n + 32];
            v = wred32(v);
            if (n == 0) g_dsum[i] = v;
        }
    } else {
        int t = (blockIdx.x - 256) * 256 + threadIdx.x;
        if (t >= 1024) return;
        int lane = t & 31;
        int kk = (t >> 5) & 3;
        int nt = t >> 7;
        int n  = nt * 8 + (lane >> 2);
        int kq = kk * 16 + (lane & 3) * 2;
        uint2 r;
        r.x = pack_h2(W2[kq * HH + n],       W2[(kq + 1) * HH + n]);
        r.y = pack_h2(W2[(kq + 8) * HH + n], W2[(kq + 9) * HH + n]);
        g_w2f[t] = r;
    }
}

// ---------------- main pair kernel ----------------
__global__ __launch_bounds__(128, 5) void pair_kernel(
    const float* __restrict__ g1, const float* __restrict__ be1,
    const float* __restrict__ b2, const float* __restrict__ g2,
    const float* __restrict__ be2, const float* __restrict__ W3,
    const float* __restrict__ b3, float* __restrict__ out) {
    __shared__ uint2 s_bf[8 * 4 * 32];
    __shared__ __align__(16) float s_hd[16 * PADH];
    __shared__ __align__(16) float s_hs[8 * PADH];
    __shared__ __align__(8) float s_g1[HH];
    __shared__ __align__(8) float s_be1[HH];
    __shared__ __align__(8) float s_b2[HH];
    __shared__ __align__(8) float s_g2[HH];
    __shared__ __align__(8) float s_be2[HH];
    __shared__ __align__(8) float s_w3[HH];
    __shared__ float s_S[8], s_T[16], s_b3;

    int tid = threadIdx.x;
    int w = tid >> 5, lane = tid & 31;
    int qr = lane >> 2, qc = lane & 3;
    int bx = blockIdx.x, by = blockIdx.y;

    #pragma unroll
    for (int idx = tid; idx < 1024; idx += 128) s_bf[idx] = g_w2f[idx];
    #pragma unroll
    for (int idx = tid; idx < 16 * 64; idx += 128) {
        int r = idx >> 6, c = idx & 63;
        s_hd[r * PADH + c] = g_hd[(bx * 16 + r) * HH + c];
    }
    #pragma unroll
    for (int idx = tid; idx < 8 * 64; idx += 128) {
        int r = idx >> 6, c = idx & 63;
        s_hs[r * PADH + c] = g_hs[(by * 8 + r) * HH + c];
    }
    if (tid < HH) {
        s_g1[tid]  = g1[tid];
        s_be1[tid] = be1[tid];
        s_b2[tid]  = b2[tid];
        s_g2[tid]  = g2[tid];
        s_be2[tid] = be2[tid];
        s_w3[tid]  = W3[tid];
    }
    if (tid < 8)  s_S[tid] = g_hsum[by * 8 + tid];
    if (tid < 16) s_T[tid] = g_dsum[bx * 16 + tid];
    if (tid == 0) s_b3 = b3[0];
    __syncthreads();

    const float* hdr1 = s_hd + qr * PADH;
    const float* hdr2 = s_hd + (qr + 8) * PADH;
    float Tv1 = s_T[qr], Tv2 = s_T[qr + 8];

    // ---- prologue: packed LN1 -> fp16 A frags (hd re-read from smem, not cached) ----
    uint32_t af[2][4][4];
    #pragma unroll
    for (int mt = 0; mt < 2; mt++) {
        const float* hsr = s_hs + (w * 2 + mt) * PADH;
        ull a[8];
        #pragma unroll
        for (int ci = 0; ci < 8; ci++) {
            int c = (ci >> 1) * 16 + (ci & 1) * 8 + qc * 2;
            a[ci] = *reinterpret_cast<const ull*>(hsr + c);   // quad-broadcast, cheap
        }
        float Sv = s_S[w * 2 + mt];
        #pragma unroll
        for (int rr = 0; rr < 2; rr++) {
            const float* hdr = rr ? hdr2 : hdr1;
            float Tv = rr ? Tv2 : Tv1;
            ull x[8];
            ull s2p = 0ull;
            #pragma unroll
            for (int ci = 0; ci < 8; ci++) {
                int c = (ci >> 1) * 16 + (ci & 1) * 8 + qc * 2;
                ull d = *reinterpret_cast<const ull*>(hdr + c);
                x[ci] = p2_add(a[ci], d);
                s2p = p2_fma(x[ci], x[ci], s2p);
            }
            float lo, hi;
            p2_unpack(s2p, lo, hi);
            float s2 = qred(lo + hi);
            float mu = (Sv + Tv) * (1.f / HH);
            float rs = rsqrtf(s2 * (1.f / HH) - mu * mu + LN_EPS);
            ull rsp = p2_pack(rs, rs);
            ull nmp = p2_pack(-mu * rs, -mu * rs);
            #pragma unroll
            for (int ci = 0; ci < 8; ci++) {
                int kk = ci >> 1, h = ci & 1;
                int c = kk * 16 + h * 8 + qc * 2;
                ull gp = *reinterpret_cast<const ull*>(s_g1 + c);
                ull bp = *reinterpret_cast<const ull*>(s_be1 + c);
                ull v = p2_fma(p2_fma(x[ci], rsp, nmp), gp, bp);
                float va, vb;
                p2_unpack(v, va, vb);
                af[mt][kk][h * 2 + rr] = pack_h2(fmaxf(va, 0.f), fmaxf(vb, 0.f));
            }
        }
    }

    // ---- fused MMA, acc initialized with b2 ----
    float acc[2][8][4];
    #pragma unroll
    for (int nt = 0; nt < 8; nt++) {
        int c = nt * 8 + qc * 2;
        ull b2p = *reinterpret_cast<const ull*>(s_b2 + c);
        float bxv, byv;
        p2_unpack(b2p, bxv, byv);
        #pragma unroll
        for (int mt = 0; mt < 2; mt++) {
            acc[mt][nt][0] = bxv; acc[mt][nt][1] = byv;
            acc[mt][nt][2] = bxv; acc[mt][nt][3] = byv;
        }
    }
    #pragma unroll
    for (int nt = 0; nt < 8; nt++) {
        #pragma unroll
        for (int kk = 0; kk < 4; kk++) {
            uint2 B = s_bf[(nt * 4 + kk) * 32 + lane];
            mma_f16(acc[0][nt], af[0][kk][0], af[0][kk][1], af[0][kk][2], af[0][kk][3], B.x, B.y);
            mma_f16(acc[1][nt], af[1][kk][0], af[1][kk][1], af[1][kk][2], af[1][kk][3], B.x, B.y);
        }
    }

    // ---- epilogue per mtile (re-pack from acc; no persistent u arrays) ----
    #pragma unroll
    for (int mt = 0; mt < 2; mt++) {
        int i  = by * 8 + w * 2 + mt;
        int j1 = bx * 16 + qr;

        ull t11p = 0ull, t12p = 0ull, t21p = 0ull, t22p = 0ull;
        #pragma unroll
        for (int nt = 0; nt < 8; nt++) {
            ull ua = p2_pack(acc[mt][nt][0], acc[mt][nt][1]);
            ull ub = p2_pack(acc[mt][nt][2], acc[mt][nt][3]);
            t11p = p2_add(t11p, ua); t12p = p2_fma(ua, ua, t12p);
            t21p = p2_add(t21p, ub); t22p = p2_fma(ub, ub, t22p);
        }
        float lo, hi;
        p2_unpack(t11p, lo, hi); float t11 = qred(lo + hi);
        p2_unpack(t12p, lo, hi); float t12 = qred(lo + hi);
        p2_unpack(t21p, lo, hi); float t21 = qred(lo + hi);
        p2_unpack(t22p, lo, hi); float t22 = qred(lo + hi);
        float m1 = t11 * (1.f / HH);
        float r1 = rsqrtf(t12 * (1.f / HH) - m1 * m1 + LN_EPS);
        float m2 = t21 * (1.f / HH);
        float r2 = rsqrtf(t22 * (1.f / HH) - m2 * m2 + LN_EPS);
        ull r1p = p2_pack(r1, r1), nm1p = p2_pack(-m1 * r1, -m1 * r1);
        ull r2p = p2_pack(r2, r2), nm2p = p2_pack(-m2 * r2, -m2 * r2);

        ull d1p = 0ull, d2p = 0ull;
        #pragma unroll
        for (int nt = 0; nt < 8; nt++) {
            int c = nt * 8 + qc * 2;
            ull g2p  = *reinterpret_cast<const ull*>(s_g2 + c);
            ull be2p = *reinterpret_cast<const ull*>(s_be2 + c);
            ull w3p  = *reinterpret_cast<const ull*>(s_w3 + c);
            ull ua = p2_pack(acc[mt][nt][0], acc[mt][nt][1]);
            ull ub = p2_pack(acc[mt][nt][2], acc[mt][nt][3]);
            float za, zb;
            ull z1 = p2_fma(p2_fma(ua, r1p, nm1p), g2p, be2p);
            p2_unpack(z1, za, zb);
            d1p = p2_fma(p2_pack(fmaxf(za, 0.f), fmaxf(zb, 0.f)), w3p, d1p);
            ull z2 = p2_fma(p2_fma(ub, r2p, nm2p), g2p, be2p);
            p2_unpack(z2, za, zb);
            d2p = p2_fma(p2_pack(fmaxf(za, 0.f), fmaxf(zb, 0.f)), w3p, d2p);
        }
        p2_unpack(d1p, lo, hi); float d1 = qred(lo + hi);
        p2_unpack(d2p, lo, hi); float d2 = qred(lo + hi);
        if (qc == 0) {
            out[i * NN + j1]     = 1.f / (1.f + __expf(-(d1 + s_b3)));
            out[i * NN + j1 + 8] = 1.f / (1.f + __expf(-(d2 + s_b3)));
        }
    }
}

// ---------------- launch ----------------
extern "C" void kernel_launch(void* const* d_in, const int* in_sizes, int n_in,
                              void* d_out, int out_size) {
    const float* X   = (const float*)d_in[0];
    const float* W1  = (const float*)d_in[1];
    const float* b1  = (const float*)d_in[2];
    const float* g1  = (const float*)d_in[3];
    const float* be1 = (const float*)d_in[4];
    const float* W2  = (const float*)d_in[5];
    const float* b2  = (const float*)d_in[6];
    const float* g2  = (const float*)d_in[7];
    const float* be2 = (const float*)d_in[8];
    const float* W3  = (const float*)d_in[9];
    const float* b3  = (const float*)d_in[10];
    float* out = (float*)d_out;

    prep_all<<<260, 256>>>(X, W1, b1, W2);
    dim3 grid(NN / 16, NN / 8);
    pair_kernel<<<grid, 128>>>(g1, be1, b2, g2, be2, W3, b3, out);
}